// round 14
// baseline (speedup 1.0000x reference)
#include <cuda_runtime.h>
#include <cuda_fp16.h>
#include <math_constants.h>
#include <cstdint>

static constexpr int B  = 4;
static constexpr int S  = 1024;
static constexpr int D  = 768;
static constexpr int H  = 12;
static constexpr int DK = 64;
static constexpr int M  = B * S;   // 4096
static constexpr int KD = 768;

// ----------------- scratch (device globals; no allocs allowed) -----------------
__device__ __half g_aqh[M*D], g_aql[M*D];     // query hi/lo fp16
__device__ __half g_akh[M*D], g_akl[M*D];
__device__ __half g_av [M*D];                 // value single fp16
__device__ __half g_ath[2*M*D], g_atl[2*M*D];
__device__ __half g_w[5*D*D];                 // Wq,Wk,Wv,Wt,Wo single fp16
__device__ __half g_Qf [M*D];                 // Q head layout, single fp16
__device__ float  g_Kf [M*D];                 // K head fp32; reused later as xsum (fp16)
__device__ __half g_Vf [M*D];                 // V head layout fp16
__device__ __half g_K0f[M*D], g_K1f[M*D];     // KT_t = 0.125*log2e*(T'+K), fp16
__device__ __half g_xf [2*M*D];               // attention out partials (t=0, t=1)

static constexpr float KT_SCALE = 0.125f * 1.4426950408889634f;   // fold log2e

// ----------------- PTX helpers (baseline ISA, sm_80-level) -----------------
__device__ __forceinline__ uint32_t smem_u32(const void* p) {
    return (uint32_t)__cvta_generic_to_shared(p);
}
__device__ __forceinline__ void cp16(uint32_t dst, const void* src) {
    asm volatile("cp.async.cg.shared.global [%0], [%1], 16;" :: "r"(dst), "l"(src));
}
__device__ __forceinline__ void cp_commit() {
    asm volatile("cp.async.commit_group;" ::: "memory");
}
__device__ __forceinline__ void ldm_x4(uint32_t* r, uint32_t addr) {
    asm volatile("ldmatrix.sync.aligned.m8n8.x4.shared.b16 {%0,%1,%2,%3}, [%4];"
                 : "=r"(r[0]), "=r"(r[1]), "=r"(r[2]), "=r"(r[3]) : "r"(addr));
}
__device__ __forceinline__ void ldm_x4t(uint32_t* r, uint32_t addr) {
    asm volatile("ldmatrix.sync.aligned.m8n8.x4.trans.shared.b16 {%0,%1,%2,%3}, [%4];"
                 : "=r"(r[0]), "=r"(r[1]), "=r"(r[2]), "=r"(r[3]) : "r"(addr));
}
__device__ __forceinline__ void mma16816f(float* c, const uint32_t* a, const uint32_t* b) {
    asm volatile("mma.sync.aligned.m16n8k16.row.col.f32.f16.f16.f32 "
                 "{%0,%1,%2,%3},{%4,%5,%6,%7},{%8,%9},{%0,%1,%2,%3};"
                 : "+f"(c[0]), "+f"(c[1]), "+f"(c[2]), "+f"(c[3])
                 : "r"(a[0]), "r"(a[1]), "r"(a[2]), "r"(a[3]), "r"(b[0]), "r"(b[1]));
}
__device__ __forceinline__ void split1h(float f, __half& h, __half& l) {
    h = __float2half_rn(f);
    l = __float2half_rn(f - __half2float(h));
}
__device__ __forceinline__ uint32_t packh2(float a, float b) {
    __half2 h = __floats2half2_rn(a, b);
    return *(uint32_t*)&h;
}

// ----------------- batched fp32 -> fp16 convert (hi/lo for seg<3, single else) -----------------
struct CvtBatch {
    const float* src[9];
    __half* hi[9];
    __half* lo[9];
    int n4[9];
    int nblk[9];
};
__global__ void __launch_bounds__(256)
cvt_batch(CvtBatch a)
{
    int bx = blockIdx.x, seg = 0;
#pragma unroll
    for (int sIt = 0; sIt < 8; sIt++) {
        if (bx >= a.nblk[seg]) { bx -= a.nblk[seg]; seg++; }
    }
    const int base = bx * 1024 + threadIdx.x;
#pragma unroll
    for (int q = 0; q < 4; q++) {
        const int i = base + q * 256;
        if (i >= a.n4[seg]) continue;
        float4 v = ((const float4*)a.src[seg])[i];
        if (seg < 3) {
            __half h0,l0,h1,l1,h2,l2,h3,l3;
            split1h(v.x,h0,l0); split1h(v.y,h1,l1);
            split1h(v.z,h2,l2); split1h(v.w,h3,l3);
            ((__half2*)a.hi[seg])[2*i+0] = __halves2half2(h0, h1);
            ((__half2*)a.hi[seg])[2*i+1] = __halves2half2(h2, h3);
            ((__half2*)a.lo[seg])[2*i+0] = __halves2half2(l0, l1);
            ((__half2*)a.lo[seg])[2*i+1] = __halves2half2(l2, l3);
        } else {
            ((__half2*)a.hi[seg])[2*i+0] = __floats2half2_rn(v.x, v.y);
            ((__half2*)a.hi[seg])[2*i+1] = __floats2half2_rn(v.z, v.w);
        }
    }
}

// ----------------- combine: xsum = x0 + x1 (fp16) -----------------
__global__ void __launch_bounds__(256)
combine_x(const uint4* __restrict__ x0, const uint4* __restrict__ x1,
          uint4* __restrict__ xs, int n)
{
    int i = blockIdx.x * blockDim.x + threadIdx.x;
    if (i >= n) return;
    uint4 a = x0[i], b = x1[i], r;
    const __half2* pa = (const __half2*)&a;
    const __half2* pb = (const __half2*)&b;
    __half2* pr = (__half2*)&r;
#pragma unroll
    for (int k = 0; k < 4; k++) pr[k] = __hadd2(pa[k], pb[k]);
    xs[i] = r;
}

// ----------------- unified fp16 GEMM (split-A iff Al != null), BK=64 staging -----------------
// modes: 1=K fp32 head; 2=fp16 single head; 3=KT fp16 head = KT_SCALE*(acc+bias+Kf32);
//        4=fp32 [M,768]+bias
static constexpr int GST = 72;
static constexpr int GTILE = 128 * GST;
static constexpr int GEMM_SMEM = 2 * 3 * GTILE * 2;    // 110592 B

struct GB {
    const __half* Ah[3]; const __half* Al[3]; const __half* W[3];
    const float* bias[3];
    const float* addK[3];
    void* o0[3];
    int mode[3];
};

__global__ void __launch_bounds__(256, 2)
gemmU(GB g)
{
    extern __shared__ __align__(16) __half sm[];
    const int z   = blockIdx.z;
    const int tid = threadIdx.x;
    const int l   = tid & 31;
    const int wid = tid >> 5;
    const int wm  = wid & 3;
    const int wn  = wid >> 2;
    const int m0  = blockIdx.y * 128;
    const int n0  = blockIdx.x * 128;
    const uint32_t smb = smem_u32(sm);

    const __half* Ah = g.Ah[z]; const __half* Al = g.Al[z]; const __half* W = g.W[z];
    const bool hasAl = (Al != nullptr);

    float acc[2][8][4];
#pragma unroll
    for (int i = 0; i < 2; i++)
#pragma unroll
        for (int j = 0; j < 8; j++)
#pragma unroll
            for (int q = 0; q < 4; q++) acc[i][j][q] = 0.f;

    auto load_stage = [&](int c64, int buf) {
        const int kc = c64 * 64;
        const uint32_t sb = smb + (uint32_t)buf * 3 * GTILE * 2;
        if (hasAl) {
            const __half* gsrc[3] = {
                Ah + (size_t)m0 * KD, Al + (size_t)m0 * KD, W + (size_t)n0 * KD };
#pragma unroll
            for (int i = 0; i < 12; i++) {
                int idx = tid + 256*i;
                int tile = idx >> 10, r = (idx >> 3) & 127, cc = idx & 7;
                cp16(sb + (uint32_t)(tile*GTILE + r*GST + cc*8)*2,
                     gsrc[tile] + (size_t)r * KD + kc + cc*8);
            }
        } else {
            const __half* gsrc[2] = { Ah + (size_t)m0 * KD, W + (size_t)n0 * KD };
#pragma unroll
            for (int i = 0; i < 8; i++) {
                int idx = tid + 256*i;
                int tile = idx >> 10, r = (idx >> 3) & 127, cc = idx & 7;
                cp16(sb + (uint32_t)(tile*2*GTILE + r*GST + cc*8)*2,   // slots 0 and 2
                     gsrc[tile] + (size_t)r * KD + kc + cc*8);
            }
        }
    };

    load_stage(0, 0);
    cp_commit();

    const int NC = KD / 64;   // 12
    for (int c = 0; c < NC; ++c) {
        const int buf = c & 1;
        if (c + 1 < NC) {
            load_stage(c + 1, buf ^ 1);
            cp_commit();
            asm volatile("cp.async.wait_group 1;" ::: "memory");
        } else {
            asm volatile("cp.async.wait_group 0;" ::: "memory");
        }
        __syncthreads();

        const uint32_t sb = smb + (uint32_t)buf * 3 * GTILE * 2;
        const uint32_t uAh = sb, uAl = sb + GTILE*2, uW = sb + 2*GTILE*2;

#pragma unroll
        for (int kk = 0; kk < 4; kk++) {
            uint32_t af[2][2][4];
            const uint32_t a_off =
                (uint32_t)((wm*32 + (l & 15)) * GST + kk*16 + (l >> 4)*8) * 2;
#pragma unroll
            for (int mt = 0; mt < 2; mt++) {
                ldm_x4(af[0][mt], uAh + a_off + (uint32_t)(mt*16*GST)*2);
                if (hasAl) ldm_x4(af[1][mt], uAl + a_off + (uint32_t)(mt*16*GST)*2);
            }
            const uint32_t b_off =
                (uint32_t)((wn*64 + ((l >> 4) ? 8 : 0) + (l & 7)) * GST
                           + kk*16 + (((l >> 3) & 1) ? 8 : 0)) * 2;
#pragma unroll
            for (int jp = 0; jp < 4; jp++) {
                uint32_t bW[4];
                ldm_x4(bW, uW + b_off + (uint32_t)(jp*16*GST)*2);
#pragma unroll
                for (int mt = 0; mt < 2; mt++) {
                    mma16816f(acc[mt][2*jp],   af[0][mt], bW+0);
                    mma16816f(acc[mt][2*jp+1], af[0][mt], bW+2);
                    if (hasAl) {
                        mma16816f(acc[mt][2*jp],   af[1][mt], bW+0);
                        mma16816f(acc[mt][2*jp+1], af[1][mt], bW+2);
                    }
                }
            }
        }
        __syncthreads();
    }

    const float* bias = g.bias[z];
    const int mode = g.mode[z];
#pragma unroll
    for (int mt = 0; mt < 2; mt++) {
        const int rA = m0 + wm*32 + mt*16 + (l >> 2);
        const int rB = rA + 8;
#pragma unroll
        for (int j = 0; j < 8; j++) {
            const int col = n0 + wn*64 + j*8 + (l & 3)*2;
            const float bx = __ldg(bias + col), by = __ldg(bias + col + 1);
            float2 pa = make_float2(acc[mt][j][0] + bx, acc[mt][j][1] + by);
            float2 pb = make_float2(acc[mt][j][2] + bx, acc[mt][j][3] + by);
            if (mode == 4) {
                *(float2*)((float*)g.o0[z] + (size_t)rA*D + col) = pa;
                *(float2*)((float*)g.o0[z] + (size_t)rB*D + col) = pb;
                continue;
            }
            const int hI = col >> 6, dI = col & 63;
            const int bA = rA >> 10, sA_ = rA & (S-1);
            const int bB = rB >> 10, sB_ = rB & (S-1);
            const size_t oiA = (((size_t)(bA*H + hI))*S + sA_)*DK + dI;
            const size_t oiB = (((size_t)(bB*H + hI))*S + sB_)*DK + dI;
            if (mode == 1) {
                *(float2*)((float*)g.o0[z] + oiA) = pa;
                *(float2*)((float*)g.o0[z] + oiB) = pb;
            } else if (mode == 2) {
                *(__half2*)((__half*)g.o0[z] + oiA) = __floats2half2_rn(pa.x, pa.y);
                *(__half2*)((__half*)g.o0[z] + oiB) = __floats2half2_rn(pb.x, pb.y);
            } else {   // mode 3: KT = KT_SCALE*(acc+bias+K)
                float2 kA = *(const float2*)(g.addK[z] + oiA);
                float2 kB = *(const float2*)(g.addK[z] + oiB);
                *(__half2*)((__half*)g.o0[z] + oiA) =
                    __floats2half2_rn(KT_SCALE*(pa.x + kA.x), KT_SCALE*(pa.y + kA.y));
                *(__half2*)((__half*)g.o0[z] + oiB) =
                    __floats2half2_rn(KT_SCALE*(pb.x + kB.x), KT_SCALE*(pb.y + kB.y));
            }
        }
    }
}

// ----------------- fp16 flash attention, one time-stream per CTA (2 CTA/SM) -----------------
static constexpr int AST = 72;
static constexpr int Q_HALVES  = 128 * AST;
static constexpr int KT_HALVES = 128 * AST;
static constexpr int SUB_HALVES = 64 * AST;
static constexpr int TILE2     = 2 * KT_HALVES;             // Kt, Vf
static constexpr int ATTN_SMEM = (Q_HALVES + 2*TILE2) * 2;  // 92160 B

__global__ void __launch_bounds__(256, 2)
attn_mma(const __half* __restrict__ Qf,
         const __half* __restrict__ K0f, const __half* __restrict__ K1f,
         const __half* __restrict__ Vf,
         __half* __restrict__ X)
{
    extern __shared__ __align__(16) __half smA[];
    const int tid = threadIdx.x;
    const int l   = tid & 31;
    const int w   = tid >> 5;
    const int q0w = w * 16;
    const int q0b = blockIdx.x * 128;
    const int h   = blockIdx.y;
    const int t   = blockIdx.z & 1;
    const int b   = blockIdx.z >> 1;
    const size_t bh = ((size_t)(b*H + h)) * S * DK;
    const __half* Kt = t ? K1f : K0f;

    const uint32_t uQ0 = smem_u32(smA);
    const uint32_t uT  = uQ0 + Q_HALVES*2;

#pragma unroll
    for (int i = 0; i < 4; i++) {
        int idx = tid + 256*i;
        int r = idx >> 3, c = idx & 7;
        cp16(uQ0 + (uint32_t)(r*AST + c*8)*2, Qf + bh + (size_t)(q0b + r)*DK + c*8);
    }
    cp_commit();

    auto issue = [&](int kvi, int bufi) {
        const int kv = kvi * 128;
        const __half* srcs[2] = { Kt, Vf };
        const uint32_t base = uT + (uint32_t)bufi * TILE2 * 2;
#pragma unroll
        for (int i = 0; i < 8; i++) {
            int idx = tid + 256*i;
            int tile = idx >> 10, r = (idx >> 3) & 127, c = idx & 7;
            cp16(base + (uint32_t)(tile*KT_HALVES + r*AST + c*8)*2,
                 srcs[tile] + bh + (size_t)(kv + r)*DK + c*8);
        }
    };

    issue(0, 0);
    cp_commit();

    asm volatile("cp.async.wait_group 1;" ::: "memory");
    __syncthreads();
    uint32_t qF[4][4];
#pragma unroll
    for (int kk = 0; kk < 4; kk++) {
        const uint32_t a_off = (uint32_t)((q0w + (l & 15))*AST + kk*16 + (l >> 4)*8) * 2;
        ldm_x4(qF[kk], uQ0 + a_off);
    }

    float o[8][4];
#pragma unroll
    for (int j = 0; j < 8; j++)
#pragma unroll
        for (int c = 0; c < 4; c++) o[j][c] = 0.f;
    float lA = 0.f, lB = 0.f;

    for (int it = 0; it < 8; ++it) {
        const int bufi = it & 1;
        if (it + 1 < 8) {
            issue(it + 1, bufi ^ 1);
            cp_commit();
            asm volatile("cp.async.wait_group 1;" ::: "memory");
        } else {
            asm volatile("cp.async.wait_group 0;" ::: "memory");
        }
        __syncthreads();

        const uint32_t tb = uT + (uint32_t)bufi * TILE2 * 2;

#pragma unroll
        for (int sub = 0; sub < 2; ++sub) {
            const uint32_t so = (uint32_t)(sub * SUB_HALVES) * 2;
            const uint32_t uK = tb + so;
            const uint32_t uV = tb + KT_HALVES*2 + so;

            float s[8][4];
#pragma unroll
            for (int j = 0; j < 8; j++)
#pragma unroll
                for (int c = 0; c < 4; c++) s[j][c] = 0.f;

#pragma unroll
            for (int kk = 0; kk < 4; kk++) {
                const uint32_t b_off =
                    (uint32_t)((((l >> 4) ? 8 : 0) + (l & 7))*AST + kk*16 + (((l >> 3) & 1) ? 8 : 0)) * 2;
#pragma unroll
                for (int np = 0; np < 4; np++) {
                    uint32_t bK[4];
                    ldm_x4(bK, uK + b_off + (uint32_t)(np*16*AST)*2);
                    mma16816f(s[2*np],   qF[kk], bK+0);
                    mma16816f(s[2*np+1], qF[kk], bK+2);
                }
            }

#pragma unroll
            for (int j = 0; j < 8; j++) {
                s[j][0] = exp2f(s[j][0]); s[j][1] = exp2f(s[j][1]);
                s[j][2] = exp2f(s[j][2]); s[j][3] = exp2f(s[j][3]);
                lA += s[j][0] + s[j][1];  lB += s[j][2] + s[j][3];
            }

#pragma unroll
            for (int kkp = 0; kkp < 4; kkp++) {
                uint32_t a0[4];
                a0[0] = packh2(s[2*kkp][0],   s[2*kkp][1]);
                a0[1] = packh2(s[2*kkp][2],   s[2*kkp][3]);
                a0[2] = packh2(s[2*kkp+1][0], s[2*kkp+1][1]);
                a0[3] = packh2(s[2*kkp+1][2], s[2*kkp+1][3]);
                const uint32_t b_off =
                    (uint32_t)((kkp*16 + (((l >> 3) & 1) ? 8 : 0) + (l & 7))*AST
                               + ((l >> 4) ? 8 : 0)) * 2;
#pragma unroll
                for (int np = 0; np < 4; np++) {
                    uint32_t bV[4];
                    ldm_x4t(bV, uV + b_off + (uint32_t)(np*16)*2);
                    mma16816f(o[2*np],   a0, bV+0);
                    mma16816f(o[2*np+1], a0, bV+2);
                }
            }
        }
        __syncthreads();
    }

    lA += __shfl_xor_sync(0xffffffffu, lA, 1);
    lA += __shfl_xor_sync(0xffffffffu, lA, 2);
    lB += __shfl_xor_sync(0xffffffffu, lB, 1);
    lB += __shfl_xor_sync(0xffffffffu, lB, 2);
    const float iA = 1.f/lA, iB = 1.f/lB;

    __half* Xt = X + (size_t)t * M * D;
    const int rowA = b*S + q0b + q0w + (l >> 2);
    const int rowB = rowA + 8;
    const int colB0 = h*64 + (l & 3)*2;
#pragma unroll
    for (int j = 0; j < 8; j++) {
        const int col = colB0 + j*8;
        *(__half2*)(Xt + (size_t)rowA*D + col) =
            __floats2half2_rn(o[j][0]*iA, o[j][1]*iA);
        *(__half2*)(Xt + (size_t)rowB*D + col) =
            __floats2half2_rn(o[j][2]*iB, o[j][3]*iB);
    }
}

// ----------------- launcher -----------------
extern "C" void kernel_launch(void* const* d_in, const int* in_sizes, int n_in,
                              void* d_out, int out_size)
{
    const float* query = (const float*)d_in[0];
    const float* key   = (const float*)d_in[1];
    const float* value = (const float*)d_in[2];
    const float* times = (const float*)d_in[3];
    const float* Wq = (const float*)d_in[4];  const float* bq = (const float*)d_in[5];
    const float* Wk = (const float*)d_in[6];  const float* bk = (const float*)d_in[7];
    const float* Wv = (const float*)d_in[8];  const float* bv = (const float*)d_in[9];
    const float* Wt = (const float*)d_in[10]; const float* bt = (const float*)d_in[11];
    const float* Wo = (const float*)d_in[12]; const float* bo = (const float*)d_in[13];
    float* out = (float*)d_out;

    __half *aqh,*aql,*akh,*akl,*av,*ath,*atl,*w;
    __half *Qf,*Vf,*K0f,*K1f,*xf;
    float *Kf;
    cudaGetSymbolAddress((void**)&aqh, g_aqh); cudaGetSymbolAddress((void**)&aql, g_aql);
    cudaGetSymbolAddress((void**)&akh, g_akh); cudaGetSymbolAddress((void**)&akl, g_akl);
    cudaGetSymbolAddress((void**)&av,  g_av);
    cudaGetSymbolAddress((void**)&ath, g_ath); cudaGetSymbolAddress((void**)&atl, g_atl);
    cudaGetSymbolAddress((void**)&w,   g_w);
    cudaGetSymbolAddress((void**)&Qf,  g_Qf);
    cudaGetSymbolAddress((void**)&Kf,  g_Kf);
    cudaGetSymbolAddress((void**)&Vf,  g_Vf);
    cudaGetSymbolAddress((void**)&K0f, g_K0f); cudaGetSymbolAddress((void**)&K1f, g_K1f);
    cudaGetSymbolAddress((void**)&xf,  g_xf);

    cudaFuncSetAttribute(gemmU,    cudaFuncAttributeMaxDynamicSharedMemorySize, GEMM_SMEM);
    cudaFuncSetAttribute(attn_mma, cudaFuncAttributeMaxDynamicSharedMemorySize, ATTN_SMEM);

    // ---- one batched convert launch: segs 0-2 hi/lo (q,k,times); 3 single (value); 4-8 weights
    CvtBatch cb;
    const int n4_in = M*D/4, n4_t = 2*M*D/4, n4_w = D*D/4;
    const float* srcs[9] = { query, key, times, value, Wq, Wk, Wv, Wt, Wo };
    __half* his[9] = { aqh, akh, ath, av,
        w+0*(size_t)D*D, w+1*(size_t)D*D, w+2*(size_t)D*D, w+3*(size_t)D*D, w+4*(size_t)D*D };
    __half* los[9] = { aql, akl, atl, nullptr, nullptr, nullptr, nullptr, nullptr, nullptr };
    int total_blk = 0;
    for (int i = 0; i < 9; i++) {
        cb.src[i] = srcs[i]; cb.hi[i] = his[i]; cb.lo[i] = los[i];
        cb.n4[i]  = (i == 2) ? n4_t : (i < 4 ? n4_in : n4_w);
        cb.nblk[i] = (cb.n4[i] + 1023) / 1024;
        total_blk += cb.nblk[i];
    }
    cvt_batch<<<total_blk, 256>>>(cb);

    // ---- launch 1: {Q, K} projections (split-A)
    GB g3{};
    g3.Ah[0]=aqh; g3.Al[0]=aql; g3.W[0]=w+0*(size_t)D*D; g3.bias[0]=bq;
    g3.o0[0]=Qf;  g3.mode[0]=2;
    g3.Ah[1]=akh; g3.Al[1]=akl; g3.W[1]=w+1*(size_t)D*D; g3.bias[1]=bk;
    g3.o0[1]=Kf;  g3.mode[1]=1;
    gemmU<<<dim3(D/128, M/128, 2), 256, GEMM_SMEM>>>(g3);

    // ---- launch 2: {V (single-A), KT0, KT1 (split-A)}
    GB g2{};
    g2.Ah[0]=av;  g2.Al[0]=nullptr; g2.W[0]=w+2*(size_t)D*D; g2.bias[0]=bv;
    g2.o0[0]=Vf;  g2.mode[0]=2;
    g2.Ah[1]=ath;             g2.Al[1]=atl;             g2.W[1]=w+3*(size_t)D*D;
    g2.bias[1]=bt; g2.addK[1]=Kf; g2.o0[1]=K0f; g2.mode[1]=3;
    g2.Ah[2]=ath+(size_t)M*D; g2.Al[2]=atl+(size_t)M*D; g2.W[2]=w+3*(size_t)D*D;
    g2.bias[2]=bt; g2.addK[2]=Kf; g2.o0[2]=K1f; g2.mode[2]=3;
    gemmU<<<dim3(D/128, M/128, 3), 256, GEMM_SMEM>>>(g2);

    // ---- attention: one time-stream per CTA
    dim3 ga(S/128, H, B*2);
    attn_mma<<<ga, 256, ATTN_SMEM>>>(Qf, K0f, K1f, Vf, xf);

    // ---- combine partials: xsum = x0 + x1 (reuse Kf buffer as fp16 storage)
    __half* xs = (__half*)Kf;
    const int nC = M*D/8;
    combine_x<<<(nC + 255)/256, 256>>>((const uint4*)xf, (const uint4*)(xf + (size_t)M*D),
                                       (uint4*)xs, nC);

    // ---- launch 3: output projection (single-A, fp32 out)
    GB go{};
    go.Ah[0]=xs; go.Al[0]=nullptr; go.W[0]=w+4*(size_t)D*D; go.bias[0]=bo;
    go.o0[0]=out; go.mode[0]=4;
    gemmU<<<dim3(D/128, M/128, 1), 256, GEMM_SMEM>>>(go);
}

// round 15
// speedup vs baseline: 1.0080x; 1.0080x over previous
#include <cuda_runtime.h>
#include <cuda_fp16.h>
#include <math_constants.h>
#include <cstdint>

static constexpr int B  = 4;
static constexpr int S  = 1024;
static constexpr int D  = 768;
static constexpr int H  = 12;
static constexpr int DK = 64;
static constexpr int M  = B * S;   // 4096
static constexpr int KD = 768;

// ----------------- scratch (device globals; no allocs allowed) -----------------
__device__ __half g_aqh[M*D], g_aql[M*D];     // query hi/lo fp16
__device__ __half g_akh[M*D], g_akl[M*D];
__device__ __half g_av [M*D];                 // value single fp16
__device__ __half g_ath[2*M*D], g_atl[2*M*D];
__device__ __half g_w[5*D*D];                 // Wq,Wk,Wv,Wt,Wo single fp16
__device__ __half g_Qf [M*D];                 // Q head layout, single fp16
__device__ float  g_Kf [M*D];                 // K head layout fp32
__device__ __half g_Vf [M*D];                 // V head layout fp16
__device__ __half g_K0f[M*D], g_K1f[M*D];     // KT_t = 0.125*log2e*(T'+K), fp16
__device__ __half g_xf [M*D];                 // attention out, single fp16

static constexpr float KT_SCALE = 0.125f * 1.4426950408889634f;   // fold log2e

// ----------------- PTX helpers (baseline ISA, sm_80-level) -----------------
__device__ __forceinline__ uint32_t smem_u32(const void* p) {
    return (uint32_t)__cvta_generic_to_shared(p);
}
__device__ __forceinline__ void cp16(uint32_t dst, const void* src) {
    asm volatile("cp.async.cg.shared.global [%0], [%1], 16;" :: "r"(dst), "l"(src));
}
__device__ __forceinline__ void cp_commit() {
    asm volatile("cp.async.commit_group;" ::: "memory");
}
__device__ __forceinline__ void ldm_x4(uint32_t* r, uint32_t addr) {
    asm volatile("ldmatrix.sync.aligned.m8n8.x4.shared.b16 {%0,%1,%2,%3}, [%4];"
                 : "=r"(r[0]), "=r"(r[1]), "=r"(r[2]), "=r"(r[3]) : "r"(addr));
}
__device__ __forceinline__ void ldm_x4t(uint32_t* r, uint32_t addr) {
    asm volatile("ldmatrix.sync.aligned.m8n8.x4.trans.shared.b16 {%0,%1,%2,%3}, [%4];"
                 : "=r"(r[0]), "=r"(r[1]), "=r"(r[2]), "=r"(r[3]) : "r"(addr));
}
__device__ __forceinline__ void mma16816f(float* c, const uint32_t* a, const uint32_t* b) {
    asm volatile("mma.sync.aligned.m16n8k16.row.col.f32.f16.f16.f32 "
                 "{%0,%1,%2,%3},{%4,%5,%6,%7},{%8,%9},{%0,%1,%2,%3};"
                 : "+f"(c[0]), "+f"(c[1]), "+f"(c[2]), "+f"(c[3])
                 : "r"(a[0]), "r"(a[1]), "r"(a[2]), "r"(a[3]), "r"(b[0]), "r"(b[1]));
}
__device__ __forceinline__ void split1h(float f, __half& h, __half& l) {
    h = __float2half_rn(f);
    l = __float2half_rn(f - __half2float(h));
}
__device__ __forceinline__ uint32_t packh2(float a, float b) {
    __half2 h = __floats2half2_rn(a, b);
    return *(uint32_t*)&h;
}

// ----------------- batched fp32 -> fp16 convert (hi/lo for seg<3, single else) -----------------
struct CvtBatch {
    const float* src[9];
    __half* hi[9];
    __half* lo[9];
    int n4[9];
    int nblk[9];
};
__global__ void __launch_bounds__(256)
cvt_batch(CvtBatch a)
{
    int bx = blockIdx.x, seg = 0;
#pragma unroll
    for (int sIt = 0; sIt < 8; sIt++) {
        if (bx >= a.nblk[seg]) { bx -= a.nblk[seg]; seg++; }
    }
    const int base = bx * 1024 + threadIdx.x;
#pragma unroll
    for (int q = 0; q < 4; q++) {
        const int i = base + q * 256;
        if (i >= a.n4[seg]) continue;
        float4 v = ((const float4*)a.src[seg])[i];
        if (seg < 3) {
            __half h0,l0,h1,l1,h2,l2,h3,l3;
            split1h(v.x,h0,l0); split1h(v.y,h1,l1);
            split1h(v.z,h2,l2); split1h(v.w,h3,l3);
            ((__half2*)a.hi[seg])[2*i+0] = __halves2half2(h0, h1);
            ((__half2*)a.hi[seg])[2*i+1] = __halves2half2(h2, h3);
            ((__half2*)a.lo[seg])[2*i+0] = __halves2half2(l0, l1);
            ((__half2*)a.lo[seg])[2*i+1] = __halves2half2(l2, l3);
        } else {
            ((__half2*)a.hi[seg])[2*i+0] = __floats2half2_rn(v.x, v.y);
            ((__half2*)a.hi[seg])[2*i+1] = __floats2half2_rn(v.z, v.w);
        }
    }
}

// ----------------- unified fp16 GEMM (split-A iff Al != null), BK=64 staging -----------------
// modes: 1=K fp32 head; 2=fp16 single head; 3=KT fp16 head = KT_SCALE*(acc+bias+Kf32);
//        4=fp32 [M,768]+bias
static constexpr int GST = 72;
static constexpr int GTILE = 128 * GST;
static constexpr int GEMM_SMEM = 2 * 3 * GTILE * 2;    // 110592 B

struct GB {
    const __half* Ah[3]; const __half* Al[3]; const __half* W[3];
    const float* bias[3];
    const float* addK[3];
    void* o0[3];
    int mode[3];
};

__global__ void __launch_bounds__(256, 2)
gemmU(GB g)
{
    extern __shared__ __align__(16) __half sm[];
    const int z   = blockIdx.z;
    const int tid = threadIdx.x;
    const int l   = tid & 31;
    const int wid = tid >> 5;
    const int wm  = wid & 3;
    const int wn  = wid >> 2;
    const int m0  = blockIdx.y * 128;
    const int n0  = blockIdx.x * 128;
    const uint32_t smb = smem_u32(sm);

    const __half* Ah = g.Ah[z]; const __half* Al = g.Al[z]; const __half* W = g.W[z];
    const bool hasAl = (Al != nullptr);

    float acc[2][8][4];
#pragma unroll
    for (int i = 0; i < 2; i++)
#pragma unroll
        for (int j = 0; j < 8; j++)
#pragma unroll
            for (int q = 0; q < 4; q++) acc[i][j][q] = 0.f;

    auto load_stage = [&](int c64, int buf) {
        const int kc = c64 * 64;
        const uint32_t sb = smb + (uint32_t)buf * 3 * GTILE * 2;
        if (hasAl) {
            const __half* gsrc[3] = {
                Ah + (size_t)m0 * KD, Al + (size_t)m0 * KD, W + (size_t)n0 * KD };
#pragma unroll
            for (int i = 0; i < 12; i++) {
                int idx = tid + 256*i;
                int tile = idx >> 10, r = (idx >> 3) & 127, cc = idx & 7;
                cp16(sb + (uint32_t)(tile*GTILE + r*GST + cc*8)*2,
                     gsrc[tile] + (size_t)r * KD + kc + cc*8);
            }
        } else {
            const __half* gsrc[2] = { Ah + (size_t)m0 * KD, W + (size_t)n0 * KD };
#pragma unroll
            for (int i = 0; i < 8; i++) {
                int idx = tid + 256*i;
                int tile = idx >> 10, r = (idx >> 3) & 127, cc = idx & 7;
                cp16(sb + (uint32_t)(tile*2*GTILE + r*GST + cc*8)*2,   // slots 0 and 2
                     gsrc[tile] + (size_t)r * KD + kc + cc*8);
            }
        }
    };

    load_stage(0, 0);
    cp_commit();

    const int NC = KD / 64;   // 12
    for (int c = 0; c < NC; ++c) {
        const int buf = c & 1;
        if (c + 1 < NC) {
            load_stage(c + 1, buf ^ 1);
            cp_commit();
            asm volatile("cp.async.wait_group 1;" ::: "memory");
        } else {
            asm volatile("cp.async.wait_group 0;" ::: "memory");
        }
        __syncthreads();

        const uint32_t sb = smb + (uint32_t)buf * 3 * GTILE * 2;
        const uint32_t uAh = sb, uAl = sb + GTILE*2, uW = sb + 2*GTILE*2;

#pragma unroll
        for (int kk = 0; kk < 4; kk++) {
            uint32_t af[2][2][4];
            const uint32_t a_off =
                (uint32_t)((wm*32 + (l & 15)) * GST + kk*16 + (l >> 4)*8) * 2;
#pragma unroll
            for (int mt = 0; mt < 2; mt++) {
                ldm_x4(af[0][mt], uAh + a_off + (uint32_t)(mt*16*GST)*2);
                if (hasAl) ldm_x4(af[1][mt], uAl + a_off + (uint32_t)(mt*16*GST)*2);
            }
            const uint32_t b_off =
                (uint32_t)((wn*64 + ((l >> 4) ? 8 : 0) + (l & 7)) * GST
                           + kk*16 + (((l >> 3) & 1) ? 8 : 0)) * 2;
#pragma unroll
            for (int jp = 0; jp < 4; jp++) {
                uint32_t bW[4];
                ldm_x4(bW, uW + b_off + (uint32_t)(jp*16*GST)*2);
#pragma unroll
                for (int mt = 0; mt < 2; mt++) {
                    mma16816f(acc[mt][2*jp],   af[0][mt], bW+0);
                    mma16816f(acc[mt][2*jp+1], af[0][mt], bW+2);
                    if (hasAl) {
                        mma16816f(acc[mt][2*jp],   af[1][mt], bW+0);
                        mma16816f(acc[mt][2*jp+1], af[1][mt], bW+2);
                    }
                }
            }
        }
        __syncthreads();
    }

    const float* bias = g.bias[z];
    const int mode = g.mode[z];
#pragma unroll
    for (int mt = 0; mt < 2; mt++) {
        const int rA = m0 + wm*32 + mt*16 + (l >> 2);
        const int rB = rA + 8;
#pragma unroll
        for (int j = 0; j < 8; j++) {
            const int col = n0 + wn*64 + j*8 + (l & 3)*2;
            const float bx = __ldg(bias + col), by = __ldg(bias + col + 1);
            float2 pa = make_float2(acc[mt][j][0] + bx, acc[mt][j][1] + by);
            float2 pb = make_float2(acc[mt][j][2] + bx, acc[mt][j][3] + by);
            if (mode == 4) {
                *(float2*)((float*)g.o0[z] + (size_t)rA*D + col) = pa;
                *(float2*)((float*)g.o0[z] + (size_t)rB*D + col) = pb;
                continue;
            }
            const int hI = col >> 6, dI = col & 63;
            const int bA = rA >> 10, sA_ = rA & (S-1);
            const int bB = rB >> 10, sB_ = rB & (S-1);
            const size_t oiA = (((size_t)(bA*H + hI))*S + sA_)*DK + dI;
            const size_t oiB = (((size_t)(bB*H + hI))*S + sB_)*DK + dI;
            if (mode == 1) {
                *(float2*)((float*)g.o0[z] + oiA) = pa;
                *(float2*)((float*)g.o0[z] + oiB) = pb;
            } else if (mode == 2) {
                *(__half2*)((__half*)g.o0[z] + oiA) = __floats2half2_rn(pa.x, pa.y);
                *(__half2*)((__half*)g.o0[z] + oiB) = __floats2half2_rn(pb.x, pb.y);
            } else {   // mode 3: KT = KT_SCALE*(acc+bias+K)
                float2 kA = *(const float2*)(g.addK[z] + oiA);
                float2 kB = *(const float2*)(g.addK[z] + oiB);
                *(__half2*)((__half*)g.o0[z] + oiA) =
                    __floats2half2_rn(KT_SCALE*(pa.x + kA.x), KT_SCALE*(pa.y + kA.y));
                *(__half2*)((__half*)g.o0[z] + oiB) =
                    __floats2half2_rn(KT_SCALE*(pb.x + kB.x), KT_SCALE*(pb.y + kB.y));
            }
        }
    }
}

// ----------------- fp16 dual-time flash attention (R13 version: both streams per CTA) -----------------
static constexpr int AST = 72;
static constexpr int Q_HALVES  = 128 * AST;
static constexpr int KT_HALVES = 128 * AST;
static constexpr int SUB_HALVES = 64 * AST;
static constexpr int TILE3     = 3 * KT_HALVES;
static constexpr int ATTN_SMEM = (Q_HALVES + 2*TILE3) * 2;   // 129024 B

__global__ void __launch_bounds__(256)
attn_mma(const __half* __restrict__ Qf,
         const __half* __restrict__ K0f, const __half* __restrict__ K1f,
         const __half* __restrict__ Vf,
         __half* __restrict__ X)
{
    extern __shared__ __align__(16) __half smA[];
    const int tid = threadIdx.x;
    const int l   = tid & 31;
    const int w   = tid >> 5;
    const int q0w = w * 16;
    const int q0b = blockIdx.x * 128;
    const int h   = blockIdx.y;
    const int b   = blockIdx.z;
    const size_t bh = ((size_t)(b*H + h)) * S * DK;

    const uint32_t uQ0 = smem_u32(smA);
    const uint32_t uT  = uQ0 + Q_HALVES*2;

#pragma unroll
    for (int i = 0; i < 4; i++) {
        int idx = tid + 256*i;
        int r = idx >> 3, c = idx & 7;
        cp16(uQ0 + (uint32_t)(r*AST + c*8)*2, Qf + bh + (size_t)(q0b + r)*DK + c*8);
    }
    cp_commit();

    auto issue = [&](int kvi, int bufi) {
        const int kv = kvi * 128;
        const __half* srcs[3] = { K0f, K1f, Vf };
        const uint32_t base = uT + (uint32_t)bufi * TILE3 * 2;
#pragma unroll
        for (int i = 0; i < 12; i++) {
            int idx = tid + 256*i;
            int tile = idx >> 10, r = (idx >> 3) & 127, c = idx & 7;
            cp16(base + (uint32_t)(tile*KT_HALVES + r*AST + c*8)*2,
                 srcs[tile] + bh + (size_t)(kv + r)*DK + c*8);
        }
    };

    issue(0, 0);
    cp_commit();

    asm volatile("cp.async.wait_group 1;" ::: "memory");
    __syncthreads();
    uint32_t qF[4][4];
#pragma unroll
    for (int kk = 0; kk < 4; kk++) {
        const uint32_t a_off = (uint32_t)((q0w + (l & 15))*AST + kk*16 + (l >> 4)*8) * 2;
        ldm_x4(qF[kk], uQ0 + a_off);
    }

    float o0[8][4], o1[8][4];
#pragma unroll
    for (int j = 0; j < 8; j++)
#pragma unroll
        for (int c = 0; c < 4; c++) { o0[j][c] = 0.f; o1[j][c] = 0.f; }
    float l0A = 0.f, l0B = 0.f, l1A = 0.f, l1B = 0.f;

    for (int it = 0; it < 8; ++it) {
        const int bufi = it & 1;
        if (it + 1 < 8) {
            issue(it + 1, bufi ^ 1);
            cp_commit();
            asm volatile("cp.async.wait_group 1;" ::: "memory");
        } else {
            asm volatile("cp.async.wait_group 0;" ::: "memory");
        }
        __syncthreads();

        const uint32_t tb = uT + (uint32_t)bufi * TILE3 * 2;

#pragma unroll
        for (int sub = 0; sub < 2; ++sub) {
            const uint32_t so  = (uint32_t)(sub * SUB_HALVES) * 2;
            const uint32_t uK0 = tb + so;
            const uint32_t uK1 = tb + KT_HALVES*2 + so;
            const uint32_t uVf = tb + 2*KT_HALVES*2 + so;

            float s0[8][4], s1[8][4];
#pragma unroll
            for (int j = 0; j < 8; j++)
#pragma unroll
                for (int c = 0; c < 4; c++) { s0[j][c] = 0.f; s1[j][c] = 0.f; }

#pragma unroll
            for (int kk = 0; kk < 4; kk++) {
                const uint32_t b_off =
                    (uint32_t)((((l >> 4) ? 8 : 0) + (l & 7))*AST + kk*16 + (((l >> 3) & 1) ? 8 : 0)) * 2;
#pragma unroll
                for (int np = 0; np < 4; np++) {
                    uint32_t bK[4];
                    ldm_x4(bK, uK0 + b_off + (uint32_t)(np*16*AST)*2);
                    mma16816f(s0[2*np],   qF[kk], bK+0);
                    mma16816f(s0[2*np+1], qF[kk], bK+2);
                    ldm_x4(bK, uK1 + b_off + (uint32_t)(np*16*AST)*2);
                    mma16816f(s1[2*np],   qF[kk], bK+0);
                    mma16816f(s1[2*np+1], qF[kk], bK+2);
                }
            }

#pragma unroll
            for (int j = 0; j < 8; j++) {
                s0[j][0] = exp2f(s0[j][0]); s0[j][1] = exp2f(s0[j][1]);
                s0[j][2] = exp2f(s0[j][2]); s0[j][3] = exp2f(s0[j][3]);
                l0A += s0[j][0] + s0[j][1];  l0B += s0[j][2] + s0[j][3];
                s1[j][0] = exp2f(s1[j][0]); s1[j][1] = exp2f(s1[j][1]);
                s1[j][2] = exp2f(s1[j][2]); s1[j][3] = exp2f(s1[j][3]);
                l1A += s1[j][0] + s1[j][1];  l1B += s1[j][2] + s1[j][3];
            }

#pragma unroll
            for (int kkp = 0; kkp < 4; kkp++) {
                uint32_t a0[4], a1[4];
                a0[0] = packh2(s0[2*kkp][0],   s0[2*kkp][1]);
                a0[1] = packh2(s0[2*kkp][2],   s0[2*kkp][3]);
                a0[2] = packh2(s0[2*kkp+1][0], s0[2*kkp+1][1]);
                a0[3] = packh2(s0[2*kkp+1][2], s0[2*kkp+1][3]);
                a1[0] = packh2(s1[2*kkp][0],   s1[2*kkp][1]);
                a1[1] = packh2(s1[2*kkp][2],   s1[2*kkp][3]);
                a1[2] = packh2(s1[2*kkp+1][0], s1[2*kkp+1][1]);
                a1[3] = packh2(s1[2*kkp+1][2], s1[2*kkp+1][3]);
                const uint32_t b_off =
                    (uint32_t)((kkp*16 + (((l >> 3) & 1) ? 8 : 0) + (l & 7))*AST
                               + ((l >> 4) ? 8 : 0)) * 2;
#pragma unroll
                for (int np = 0; np < 4; np++) {
                    uint32_t bV[4];
                    ldm_x4t(bV, uVf + b_off + (uint32_t)(np*16)*2);
                    mma16816f(o0[2*np],   a0, bV+0);
                    mma16816f(o0[2*np+1], a0, bV+2);
                    mma16816f(o1[2*np],   a1, bV+0);
                    mma16816f(o1[2*np+1], a1, bV+2);
                }
            }
        }
        __syncthreads();
    }

    l0A += __shfl_xor_sync(0xffffffffu, l0A, 1);
    l0A += __shfl_xor_sync(0xffffffffu, l0A, 2);
    l0B += __shfl_xor_sync(0xffffffffu, l0B, 1);
    l0B += __shfl_xor_sync(0xffffffffu, l0B, 2);
    l1A += __shfl_xor_sync(0xffffffffu, l1A, 1);
    l1A += __shfl_xor_sync(0xffffffffu, l1A, 2);
    l1B += __shfl_xor_sync(0xffffffffu, l1B, 1);
    l1B += __shfl_xor_sync(0xffffffffu, l1B, 2);
    const float i0A = 1.f/l0A, i0B = 1.f/l0B, i1A = 1.f/l1A, i1B = 1.f/l1B;

    const int rowA = b*S + q0b + q0w + (l >> 2);
    const int rowB = rowA + 8;
    const int colB0 = h*64 + (l & 3)*2;
#pragma unroll
    for (int j = 0; j < 8; j++) {
        const int col = colB0 + j*8;
        *(__half2*)(X + (size_t)rowA*D + col) =
            __floats2half2_rn(o0[j][0]*i0A + o1[j][0]*i1A, o0[j][1]*i0A + o1[j][1]*i1A);
        *(__half2*)(X + (size_t)rowB*D + col) =
            __floats2half2_rn(o0[j][2]*i0B + o1[j][2]*i1B, o0[j][3]*i0B + o1[j][3]*i1B);
    }
}

// ----------------- launcher -----------------
extern "C" void kernel_launch(void* const* d_in, const int* in_sizes, int n_in,
                              void* d_out, int out_size)
{
    const float* query = (const float*)d_in[0];
    const float* key   = (const float*)d_in[1];
    const float* value = (const float*)d_in[2];
    const float* times = (const float*)d_in[3];
    const float* Wq = (const float*)d_in[4];  const float* bq = (const float*)d_in[5];
    const float* Wk = (const float*)d_in[6];  const float* bk = (const float*)d_in[7];
    const float* Wv = (const float*)d_in[8];  const float* bv = (const float*)d_in[9];
    const float* Wt = (const float*)d_in[10]; const float* bt = (const float*)d_in[11];
    const float* Wo = (const float*)d_in[12]; const float* bo = (const float*)d_in[13];
    float* out = (float*)d_out;

    __half *aqh,*aql,*akh,*akl,*av,*ath,*atl,*w;
    __half *Qf,*Vf,*K0f,*K1f,*xf;
    float *Kf;
    cudaGetSymbolAddress((void**)&aqh, g_aqh); cudaGetSymbolAddress((void**)&aql, g_aql);
    cudaGetSymbolAddress((void**)&akh, g_akh); cudaGetSymbolAddress((void**)&akl, g_akl);
    cudaGetSymbolAddress((void**)&av,  g_av);
    cudaGetSymbolAddress((void**)&ath, g_ath); cudaGetSymbolAddress((void**)&atl, g_atl);
    cudaGetSymbolAddress((void**)&w,   g_w);
    cudaGetSymbolAddress((void**)&Qf,  g_Qf);
    cudaGetSymbolAddress((void**)&Kf,  g_Kf);
    cudaGetSymbolAddress((void**)&Vf,  g_Vf);
    cudaGetSymbolAddress((void**)&K0f, g_K0f); cudaGetSymbolAddress((void**)&K1f, g_K1f);
    cudaGetSymbolAddress((void**)&xf,  g_xf);

    cudaFuncSetAttribute(gemmU,    cudaFuncAttributeMaxDynamicSharedMemorySize, GEMM_SMEM);
    cudaFuncSetAttribute(attn_mma, cudaFuncAttributeMaxDynamicSharedMemorySize, ATTN_SMEM);

    // ---- one batched convert launch: segs 0-2 hi/lo (q,k,times); 3 single (value); 4-8 weights
    CvtBatch cb;
    const int n4_in = M*D/4, n4_t = 2*M*D/4, n4_w = D*D/4;
    const float* srcs[9] = { query, key, times, value, Wq, Wk, Wv, Wt, Wo };
    __half* his[9] = { aqh, akh, ath, av,
        w+0*(size_t)D*D, w+1*(size_t)D*D, w+2*(size_t)D*D, w+3*(size_t)D*D, w+4*(size_t)D*D };
    __half* los[9] = { aql, akl, atl, nullptr, nullptr, nullptr, nullptr, nullptr, nullptr };
    int total_blk = 0;
    for (int i = 0; i < 9; i++) {
        cb.src[i] = srcs[i]; cb.hi[i] = his[i]; cb.lo[i] = los[i];
        cb.n4[i]  = (i == 2) ? n4_t : (i < 4 ? n4_in : n4_w);
        cb.nblk[i] = (cb.n4[i] + 1023) / 1024;
        total_blk += cb.nblk[i];
    }
    cvt_batch<<<total_blk, 256>>>(cb);

    // ---- launch 1: {Q, K} projections (split-A)
    GB g3{};
    g3.Ah[0]=aqh; g3.Al[0]=aql; g3.W[0]=w+0*(size_t)D*D; g3.bias[0]=bq;
    g3.o0[0]=Qf;  g3.mode[0]=2;
    g3.Ah[1]=akh; g3.Al[1]=akl; g3.W[1]=w+1*(size_t)D*D; g3.bias[1]=bk;
    g3.o0[1]=Kf;  g3.mode[1]=1;
    gemmU<<<dim3(D/128, M/128, 2), 256, GEMM_SMEM>>>(g3);

    // ---- launch 2: {V (single-A), KT0, KT1 (split-A)}
    GB g2{};
    g2.Ah[0]=av;  g2.Al[0]=nullptr; g2.W[0]=w+2*(size_t)D*D; g2.bias[0]=bv;
    g2.o0[0]=Vf;  g2.mode[0]=2;
    g2.Ah[1]=ath;             g2.Al[1]=atl;             g2.W[1]=w+3*(size_t)D*D;
    g2.bias[1]=bt; g2.addK[1]=Kf; g2.o0[1]=K0f; g2.mode[1]=3;
    g2.Ah[2]=ath+(size_t)M*D; g2.Al[2]=atl+(size_t)M*D; g2.W[2]=w+3*(size_t)D*D;
    g2.bias[2]=bt; g2.addK[2]=Kf; g2.o0[2]=K1f; g2.mode[2]=3;
    gemmU<<<dim3(D/128, M/128, 3), 256, GEMM_SMEM>>>(g2);

    // ---- attention (dual-stream per CTA)
    dim3 ga(S/128, H, B);
    attn_mma<<<ga, 256, ATTN_SMEM>>>(Qf, K0f, K1f, Vf, xf);

    // ---- launch 3: output projection (single-A, fp32 out)
    GB go{};
    go.Ah[0]=xf; go.Al[0]=nullptr; go.W[0]=w+4*(size_t)D*D; go.bias[0]=bo;
    go.o0[0]=out; go.mode[0]=4;
    gemmU<<<dim3(D/128, M/128, 1), 256, GEMM_SMEM>>>(go);
}

// round 16
// speedup vs baseline: 1.0442x; 1.0359x over previous
#include <cuda_runtime.h>
#include <cuda_fp16.h>
#include <math_constants.h>
#include <cstdint>

static constexpr int B  = 4;
static constexpr int S  = 1024;
static constexpr int D  = 768;
static constexpr int H  = 12;
static constexpr int DK = 64;
static constexpr int M  = B * S;   // 4096
static constexpr int KD = 768;

// ----------------- scratch (device globals; no allocs allowed) -----------------
__device__ __half g_aqh[M*D], g_aql[M*D];     // query hi/lo fp16 (only split kept)
__device__ __half g_ak [M*D];                 // key single fp16
__device__ __half g_av [M*D];                 // value single fp16
__device__ __half g_at [2*M*D];               // times single fp16
__device__ __half g_w[5*D*D];                 // Wq,Wk,Wv,Wt,Wo single fp16
__device__ __half g_Qf [M*D];                 // Q head layout, single fp16
__device__ float  g_Kf [M*D];                 // K head layout fp32
__device__ __half g_Vf [M*D];                 // V head layout fp16
__device__ __half g_K0f[M*D], g_K1f[M*D];     // KT_t = 0.125*log2e*(T'+K), fp16
__device__ __half g_xf [M*D];                 // attention out, single fp16

static constexpr float KT_SCALE = 0.125f * 1.4426950408889634f;   // fold log2e

// ----------------- PTX helpers (baseline ISA, sm_80-level) -----------------
__device__ __forceinline__ uint32_t smem_u32(const void* p) {
    return (uint32_t)__cvta_generic_to_shared(p);
}
__device__ __forceinline__ void cp16(uint32_t dst, const void* src) {
    asm volatile("cp.async.cg.shared.global [%0], [%1], 16;" :: "r"(dst), "l"(src));
}
__device__ __forceinline__ void cp_commit() {
    asm volatile("cp.async.commit_group;" ::: "memory");
}
__device__ __forceinline__ void ldm_x4(uint32_t* r, uint32_t addr) {
    asm volatile("ldmatrix.sync.aligned.m8n8.x4.shared.b16 {%0,%1,%2,%3}, [%4];"
                 : "=r"(r[0]), "=r"(r[1]), "=r"(r[2]), "=r"(r[3]) : "r"(addr));
}
__device__ __forceinline__ void ldm_x4t(uint32_t* r, uint32_t addr) {
    asm volatile("ldmatrix.sync.aligned.m8n8.x4.trans.shared.b16 {%0,%1,%2,%3}, [%4];"
                 : "=r"(r[0]), "=r"(r[1]), "=r"(r[2]), "=r"(r[3]) : "r"(addr));
}
__device__ __forceinline__ void mma16816f(float* c, const uint32_t* a, const uint32_t* b) {
    asm volatile("mma.sync.aligned.m16n8k16.row.col.f32.f16.f16.f32 "
                 "{%0,%1,%2,%3},{%4,%5,%6,%7},{%8,%9},{%0,%1,%2,%3};"
                 : "+f"(c[0]), "+f"(c[1]), "+f"(c[2]), "+f"(c[3])
                 : "r"(a[0]), "r"(a[1]), "r"(a[2]), "r"(a[3]), "r"(b[0]), "r"(b[1]));
}
__device__ __forceinline__ void split1h(float f, __half& h, __half& l) {
    h = __float2half_rn(f);
    l = __float2half_rn(f - __half2float(h));
}
__device__ __forceinline__ uint32_t packh2(float a, float b) {
    __half2 h = __floats2half2_rn(a, b);
    return *(uint32_t*)&h;
}

// ----------------- batched fp32 -> fp16 convert (hi/lo for seg 0 only) -----------------
struct CvtBatch {
    const float* src[9];
    __half* hi[9];
    __half* lo[9];
    int n4[9];
    int nblk[9];
};
__global__ void __launch_bounds__(256)
cvt_batch(CvtBatch a)
{
    int bx = blockIdx.x, seg = 0;
#pragma unroll
    for (int sIt = 0; sIt < 8; sIt++) {
        if (bx >= a.nblk[seg]) { bx -= a.nblk[seg]; seg++; }
    }
    const int base = bx * 1024 + threadIdx.x;
#pragma unroll
    for (int q = 0; q < 4; q++) {
        const int i = base + q * 256;
        if (i >= a.n4[seg]) continue;
        float4 v = ((const float4*)a.src[seg])[i];
        if (seg < 1) {
            __half h0,l0,h1,l1,h2,l2,h3,l3;
            split1h(v.x,h0,l0); split1h(v.y,h1,l1);
            split1h(v.z,h2,l2); split1h(v.w,h3,l3);
            ((__half2*)a.hi[seg])[2*i+0] = __halves2half2(h0, h1);
            ((__half2*)a.hi[seg])[2*i+1] = __halves2half2(h2, h3);
            ((__half2*)a.lo[seg])[2*i+0] = __halves2half2(l0, l1);
            ((__half2*)a.lo[seg])[2*i+1] = __halves2half2(l2, l3);
        } else {
            ((__half2*)a.hi[seg])[2*i+0] = __floats2half2_rn(v.x, v.y);
            ((__half2*)a.hi[seg])[2*i+1] = __floats2half2_rn(v.z, v.w);
        }
    }
}

// ----------------- unified fp16 GEMM (split-A iff Al != null), BK=64 staging -----------------
// modes: 1=K fp32 head; 2=fp16 single head; 3=KT fp16 head = KT_SCALE*(acc+bias+Kf32);
//        4=fp32 [M,768]+bias
static constexpr int GST = 72;
static constexpr int GTILE = 128 * GST;
static constexpr int GEMM_SMEM = 2 * 3 * GTILE * 2;    // 110592 B

struct GB {
    const __half* Ah[3]; const __half* Al[3]; const __half* W[3];
    const float* bias[3];
    const float* addK[3];
    void* o0[3];
    int mode[3];
};

__global__ void __launch_bounds__(256, 2)
gemmU(GB g)
{
    extern __shared__ __align__(16) __half sm[];
    const int z   = blockIdx.z;
    const int tid = threadIdx.x;
    const int l   = tid & 31;
    const int wid = tid >> 5;
    const int wm  = wid & 3;
    const int wn  = wid >> 2;
    const int m0  = blockIdx.y * 128;
    const int n0  = blockIdx.x * 128;
    const uint32_t smb = smem_u32(sm);

    const __half* Ah = g.Ah[z]; const __half* Al = g.Al[z]; const __half* W = g.W[z];
    const bool hasAl = (Al != nullptr);

    float acc[2][8][4];
#pragma unroll
    for (int i = 0; i < 2; i++)
#pragma unroll
        for (int j = 0; j < 8; j++)
#pragma unroll
            for (int q = 0; q < 4; q++) acc[i][j][q] = 0.f;

    auto load_stage = [&](int c64, int buf) {
        const int kc = c64 * 64;
        const uint32_t sb = smb + (uint32_t)buf * 3 * GTILE * 2;
        if (hasAl) {
            const __half* gsrc[3] = {
                Ah + (size_t)m0 * KD, Al + (size_t)m0 * KD, W + (size_t)n0 * KD };
#pragma unroll
            for (int i = 0; i < 12; i++) {
                int idx = tid + 256*i;
                int tile = idx >> 10, r = (idx >> 3) & 127, cc = idx & 7;
                cp16(sb + (uint32_t)(tile*GTILE + r*GST + cc*8)*2,
                     gsrc[tile] + (size_t)r * KD + kc + cc*8);
            }
        } else {
            const __half* gsrc[2] = { Ah + (size_t)m0 * KD, W + (size_t)n0 * KD };
#pragma unroll
            for (int i = 0; i < 8; i++) {
                int idx = tid + 256*i;
                int tile = idx >> 10, r = (idx >> 3) & 127, cc = idx & 7;
                cp16(sb + (uint32_t)(tile*2*GTILE + r*GST + cc*8)*2,   // slots 0 and 2
                     gsrc[tile] + (size_t)r * KD + kc + cc*8);
            }
        }
    };

    load_stage(0, 0);
    cp_commit();

    const int NC = KD / 64;   // 12
    for (int c = 0; c < NC; ++c) {
        const int buf = c & 1;
        if (c + 1 < NC) {
            load_stage(c + 1, buf ^ 1);
            cp_commit();
            asm volatile("cp.async.wait_group 1;" ::: "memory");
        } else {
            asm volatile("cp.async.wait_group 0;" ::: "memory");
        }
        __syncthreads();

        const uint32_t sb = smb + (uint32_t)buf * 3 * GTILE * 2;
        const uint32_t uAh = sb, uAl = sb + GTILE*2, uW = sb + 2*GTILE*2;

#pragma unroll
        for (int kk = 0; kk < 4; kk++) {
            uint32_t af[2][2][4];
            const uint32_t a_off =
                (uint32_t)((wm*32 + (l & 15)) * GST + kk*16 + (l >> 4)*8) * 2;
#pragma unroll
            for (int mt = 0; mt < 2; mt++) {
                ldm_x4(af[0][mt], uAh + a_off + (uint32_t)(mt*16*GST)*2);
                if (hasAl) ldm_x4(af[1][mt], uAl + a_off + (uint32_t)(mt*16*GST)*2);
            }
            const uint32_t b_off =
                (uint32_t)((wn*64 + ((l >> 4) ? 8 : 0) + (l & 7)) * GST
                           + kk*16 + (((l >> 3) & 1) ? 8 : 0)) * 2;
#pragma unroll
            for (int jp = 0; jp < 4; jp++) {
                uint32_t bW[4];
                ldm_x4(bW, uW + b_off + (uint32_t)(jp*16*GST)*2);
#pragma unroll
                for (int mt = 0; mt < 2; mt++) {
                    mma16816f(acc[mt][2*jp],   af[0][mt], bW+0);
                    mma16816f(acc[mt][2*jp+1], af[0][mt], bW+2);
                    if (hasAl) {
                        mma16816f(acc[mt][2*jp],   af[1][mt], bW+0);
                        mma16816f(acc[mt][2*jp+1], af[1][mt], bW+2);
                    }
                }
            }
        }
        __syncthreads();
    }

    const float* bias = g.bias[z];
    const int mode = g.mode[z];
#pragma unroll
    for (int mt = 0; mt < 2; mt++) {
        const int rA = m0 + wm*32 + mt*16 + (l >> 2);
        const int rB = rA + 8;
#pragma unroll
        for (int j = 0; j < 8; j++) {
            const int col = n0 + wn*64 + j*8 + (l & 3)*2;
            const float bx = __ldg(bias + col), by = __ldg(bias + col + 1);
            float2 pa = make_float2(acc[mt][j][0] + bx, acc[mt][j][1] + by);
            float2 pb = make_float2(acc[mt][j][2] + bx, acc[mt][j][3] + by);
            if (mode == 4) {
                *(float2*)((float*)g.o0[z] + (size_t)rA*D + col) = pa;
                *(float2*)((float*)g.o0[z] + (size_t)rB*D + col) = pb;
                continue;
            }
            const int hI = col >> 6, dI = col & 63;
            const int bA = rA >> 10, sA_ = rA & (S-1);
            const int bB = rB >> 10, sB_ = rB & (S-1);
            const size_t oiA = (((size_t)(bA*H + hI))*S + sA_)*DK + dI;
            const size_t oiB = (((size_t)(bB*H + hI))*S + sB_)*DK + dI;
            if (mode == 1) {
                *(float2*)((float*)g.o0[z] + oiA) = pa;
                *(float2*)((float*)g.o0[z] + oiB) = pb;
            } else if (mode == 2) {
                *(__half2*)((__half*)g.o0[z] + oiA) = __floats2half2_rn(pa.x, pa.y);
                *(__half2*)((__half*)g.o0[z] + oiB) = __floats2half2_rn(pb.x, pb.y);
            } else {   // mode 3: KT = KT_SCALE*(acc+bias+K)
                float2 kA = *(const float2*)(g.addK[z] + oiA);
                float2 kB = *(const float2*)(g.addK[z] + oiB);
                *(__half2*)((__half*)g.o0[z] + oiA) =
                    __floats2half2_rn(KT_SCALE*(pa.x + kA.x), KT_SCALE*(pa.y + kA.y));
                *(__half2*)((__half*)g.o0[z] + oiB) =
                    __floats2half2_rn(KT_SCALE*(pb.x + kB.x), KT_SCALE*(pb.y + kB.y));
            }
        }
    }
}

// ----------------- fp16 dual-time flash attention (both streams per CTA) -----------------
static constexpr int AST = 72;
static constexpr int Q_HALVES  = 128 * AST;
static constexpr int KT_HALVES = 128 * AST;
static constexpr int SUB_HALVES = 64 * AST;
static constexpr int TILE3     = 3 * KT_HALVES;
static constexpr int ATTN_SMEM = (Q_HALVES + 2*TILE3) * 2;   // 129024 B

__global__ void __launch_bounds__(256)
attn_mma(const __half* __restrict__ Qf,
         const __half* __restrict__ K0f, const __half* __restrict__ K1f,
         const __half* __restrict__ Vf,
         __half* __restrict__ X)
{
    extern __shared__ __align__(16) __half smA[];
    const int tid = threadIdx.x;
    const int l   = tid & 31;
    const int w   = tid >> 5;
    const int q0w = w * 16;
    const int q0b = blockIdx.x * 128;
    const int h   = blockIdx.y;
    const int b   = blockIdx.z;
    const size_t bh = ((size_t)(b*H + h)) * S * DK;

    const uint32_t uQ0 = smem_u32(smA);
    const uint32_t uT  = uQ0 + Q_HALVES*2;

#pragma unroll
    for (int i = 0; i < 4; i++) {
        int idx = tid + 256*i;
        int r = idx >> 3, c = idx & 7;
        cp16(uQ0 + (uint32_t)(r*AST + c*8)*2, Qf + bh + (size_t)(q0b + r)*DK + c*8);
    }
    cp_commit();

    auto issue = [&](int kvi, int bufi) {
        const int kv = kvi * 128;
        const __half* srcs[3] = { K0f, K1f, Vf };
        const uint32_t base = uT + (uint32_t)bufi * TILE3 * 2;
#pragma unroll
        for (int i = 0; i < 12; i++) {
            int idx = tid + 256*i;
            int tile = idx >> 10, r = (idx >> 3) & 127, c = idx & 7;
            cp16(base + (uint32_t)(tile*KT_HALVES + r*AST + c*8)*2,
                 srcs[tile] + bh + (size_t)(kv + r)*DK + c*8);
        }
    };

    issue(0, 0);
    cp_commit();

    asm volatile("cp.async.wait_group 1;" ::: "memory");
    __syncthreads();
    uint32_t qF[4][4];
#pragma unroll
    for (int kk = 0; kk < 4; kk++) {
        const uint32_t a_off = (uint32_t)((q0w + (l & 15))*AST + kk*16 + (l >> 4)*8) * 2;
        ldm_x4(qF[kk], uQ0 + a_off);
    }

    float o0[8][4], o1[8][4];
#pragma unroll
    for (int j = 0; j < 8; j++)
#pragma unroll
        for (int c = 0; c < 4; c++) { o0[j][c] = 0.f; o1[j][c] = 0.f; }
    float l0A = 0.f, l0B = 0.f, l1A = 0.f, l1B = 0.f;

    for (int it = 0; it < 8; ++it) {
        const int bufi = it & 1;
        if (it + 1 < 8) {
            issue(it + 1, bufi ^ 1);
            cp_commit();
            asm volatile("cp.async.wait_group 1;" ::: "memory");
        } else {
            asm volatile("cp.async.wait_group 0;" ::: "memory");
        }
        __syncthreads();

        const uint32_t tb = uT + (uint32_t)bufi * TILE3 * 2;

#pragma unroll
        for (int sub = 0; sub < 2; ++sub) {
            const uint32_t so  = (uint32_t)(sub * SUB_HALVES) * 2;
            const uint32_t uK0 = tb + so;
            const uint32_t uK1 = tb + KT_HALVES*2 + so;
            const uint32_t uVf = tb + 2*KT_HALVES*2 + so;

            float s0[8][4], s1[8][4];
#pragma unroll
            for (int j = 0; j < 8; j++)
#pragma unroll
                for (int c = 0; c < 4; c++) { s0[j][c] = 0.f; s1[j][c] = 0.f; }

#pragma unroll
            for (int kk = 0; kk < 4; kk++) {
                const uint32_t b_off =
                    (uint32_t)((((l >> 4) ? 8 : 0) + (l & 7))*AST + kk*16 + (((l >> 3) & 1) ? 8 : 0)) * 2;
#pragma unroll
                for (int np = 0; np < 4; np++) {
                    uint32_t bK[4];
                    ldm_x4(bK, uK0 + b_off + (uint32_t)(np*16*AST)*2);
                    mma16816f(s0[2*np],   qF[kk], bK+0);
                    mma16816f(s0[2*np+1], qF[kk], bK+2);
                    ldm_x4(bK, uK1 + b_off + (uint32_t)(np*16*AST)*2);
                    mma16816f(s1[2*np],   qF[kk], bK+0);
                    mma16816f(s1[2*np+1], qF[kk], bK+2);
                }
            }

#pragma unroll
            for (int j = 0; j < 8; j++) {
                s0[j][0] = exp2f(s0[j][0]); s0[j][1] = exp2f(s0[j][1]);
                s0[j][2] = exp2f(s0[j][2]); s0[j][3] = exp2f(s0[j][3]);
                l0A += s0[j][0] + s0[j][1];  l0B += s0[j][2] + s0[j][3];
                s1[j][0] = exp2f(s1[j][0]); s1[j][1] = exp2f(s1[j][1]);
                s1[j][2] = exp2f(s1[j][2]); s1[j][3] = exp2f(s1[j][3]);
                l1A += s1[j][0] + s1[j][1];  l1B += s1[j][2] + s1[j][3];
            }

#pragma unroll
            for (int kkp = 0; kkp < 4; kkp++) {
                uint32_t a0[4], a1[4];
                a0[0] = packh2(s0[2*kkp][0],   s0[2*kkp][1]);
                a0[1] = packh2(s0[2*kkp][2],   s0[2*kkp][3]);
                a0[2] = packh2(s0[2*kkp+1][0], s0[2*kkp+1][1]);
                a0[3] = packh2(s0[2*kkp+1][2], s0[2*kkp+1][3]);
                a1[0] = packh2(s1[2*kkp][0],   s1[2*kkp][1]);
                a1[1] = packh2(s1[2*kkp][2],   s1[2*kkp][3]);
                a1[2] = packh2(s1[2*kkp+1][0], s1[2*kkp+1][1]);
                a1[3] = packh2(s1[2*kkp+1][2], s1[2*kkp+1][3]);
                const uint32_t b_off =
                    (uint32_t)((kkp*16 + (((l >> 3) & 1) ? 8 : 0) + (l & 7))*AST
                               + ((l >> 4) ? 8 : 0)) * 2;
#pragma unroll
                for (int np = 0; np < 4; np++) {
                    uint32_t bV[4];
                    ldm_x4t(bV, uVf + b_off + (uint32_t)(np*16)*2);
                    mma16816f(o0[2*np],   a0, bV+0);
                    mma16816f(o0[2*np+1], a0, bV+2);
                    mma16816f(o1[2*np],   a1, bV+0);
                    mma16816f(o1[2*np+1], a1, bV+2);
                }
            }
        }
        __syncthreads();
    }

    l0A += __shfl_xor_sync(0xffffffffu, l0A, 1);
    l0A += __shfl_xor_sync(0xffffffffu, l0A, 2);
    l0B += __shfl_xor_sync(0xffffffffu, l0B, 1);
    l0B += __shfl_xor_sync(0xffffffffu, l0B, 2);
    l1A += __shfl_xor_sync(0xffffffffu, l1A, 1);
    l1A += __shfl_xor_sync(0xffffffffu, l1A, 2);
    l1B += __shfl_xor_sync(0xffffffffu, l1B, 1);
    l1B += __shfl_xor_sync(0xffffffffu, l1B, 2);
    const float i0A = 1.f/l0A, i0B = 1.f/l0B, i1A = 1.f/l1A, i1B = 1.f/l1B;

    const int rowA = b*S + q0b + q0w + (l >> 2);
    const int rowB = rowA + 8;
    const int colB0 = h*64 + (l & 3)*2;
#pragma unroll
    for (int j = 0; j < 8; j++) {
        const int col = colB0 + j*8;
        *(__half2*)(X + (size_t)rowA*D + col) =
            __floats2half2_rn(o0[j][0]*i0A + o1[j][0]*i1A, o0[j][1]*i0A + o1[j][1]*i1A);
        *(__half2*)(X + (size_t)rowB*D + col) =
            __floats2half2_rn(o0[j][2]*i0B + o1[j][2]*i1B, o0[j][3]*i0B + o1[j][3]*i1B);
    }
}

// ----------------- launcher -----------------
extern "C" void kernel_launch(void* const* d_in, const int* in_sizes, int n_in,
                              void* d_out, int out_size)
{
    const float* query = (const float*)d_in[0];
    const float* key   = (const float*)d_in[1];
    const float* value = (const float*)d_in[2];
    const float* times = (const float*)d_in[3];
    const float* Wq = (const float*)d_in[4];  const float* bq = (const float*)d_in[5];
    const float* Wk = (const float*)d_in[6];  const float* bk = (const float*)d_in[7];
    const float* Wv = (const float*)d_in[8];  const float* bv = (const float*)d_in[9];
    const float* Wt = (const float*)d_in[10]; const float* bt = (const float*)d_in[11];
    const float* Wo = (const float*)d_in[12]; const float* bo = (const float*)d_in[13];
    float* out = (float*)d_out;

    __half *aqh,*aql,*ak,*av,*at,*w;
    __half *Qf,*Vf,*K0f,*K1f,*xf;
    float *Kf;
    cudaGetSymbolAddress((void**)&aqh, g_aqh); cudaGetSymbolAddress((void**)&aql, g_aql);
    cudaGetSymbolAddress((void**)&ak,  g_ak);
    cudaGetSymbolAddress((void**)&av,  g_av);
    cudaGetSymbolAddress((void**)&at,  g_at);
    cudaGetSymbolAddress((void**)&w,   g_w);
    cudaGetSymbolAddress((void**)&Qf,  g_Qf);
    cudaGetSymbolAddress((void**)&Kf,  g_Kf);
    cudaGetSymbolAddress((void**)&Vf,  g_Vf);
    cudaGetSymbolAddress((void**)&K0f, g_K0f); cudaGetSymbolAddress((void**)&K1f, g_K1f);
    cudaGetSymbolAddress((void**)&xf,  g_xf);

    cudaFuncSetAttribute(gemmU,    cudaFuncAttributeMaxDynamicSharedMemorySize, GEMM_SMEM);
    cudaFuncSetAttribute(attn_mma, cudaFuncAttributeMaxDynamicSharedMemorySize, ATTN_SMEM);

    // ---- one batched convert launch: seg0 hi/lo (query); rest single
    CvtBatch cb;
    const int n4_in = M*D/4, n4_t = 2*M*D/4, n4_w = D*D/4;
    const float* srcs[9] = { query, key, value, times, Wq, Wk, Wv, Wt, Wo };
    __half* his[9] = { aqh, ak, av, at,
        w+0*(size_t)D*D, w+1*(size_t)D*D, w+2*(size_t)D*D, w+3*(size_t)D*D, w+4*(size_t)D*D };
    __half* los[9] = { aql, nullptr, nullptr, nullptr,
        nullptr, nullptr, nullptr, nullptr, nullptr };
    int total_blk = 0;
    for (int i = 0; i < 9; i++) {
        cb.src[i] = srcs[i]; cb.hi[i] = his[i]; cb.lo[i] = los[i];
        cb.n4[i]  = (i == 3) ? n4_t : (i < 3 ? n4_in : n4_w);
        cb.nblk[i] = (cb.n4[i] + 1023) / 1024;
        total_blk += cb.nblk[i];
    }
    cvt_batch<<<total_blk, 256>>>(cb);

    // ---- launch 1: {Q (split-A), K (single-A)}
    GB g3{};
    g3.Ah[0]=aqh; g3.Al[0]=aql;    g3.W[0]=w+0*(size_t)D*D; g3.bias[0]=bq;
    g3.o0[0]=Qf;  g3.mode[0]=2;
    g3.Ah[1]=ak;  g3.Al[1]=nullptr; g3.W[1]=w+1*(size_t)D*D; g3.bias[1]=bk;
    g3.o0[1]=Kf;  g3.mode[1]=1;
    gemmU<<<dim3(D/128, M/128, 2), 256, GEMM_SMEM>>>(g3);

    // ---- launch 2: {V, KT0, KT1} (all single-A)
    GB g2{};
    g2.Ah[0]=av;  g2.Al[0]=nullptr; g2.W[0]=w+2*(size_t)D*D; g2.bias[0]=bv;
    g2.o0[0]=Vf;  g2.mode[0]=2;
    g2.Ah[1]=at;             g2.Al[1]=nullptr; g2.W[1]=w+3*(size_t)D*D;
    g2.bias[1]=bt; g2.addK[1]=Kf; g2.o0[1]=K0f; g2.mode[1]=3;
    g2.Ah[2]=at+(size_t)M*D; g2.Al[2]=nullptr; g2.W[2]=w+3*(size_t)D*D;
    g2.bias[2]=bt; g2.addK[2]=Kf; g2.o0[2]=K1f; g2.mode[2]=3;
    gemmU<<<dim3(D/128, M/128, 3), 256, GEMM_SMEM>>>(g2);

    // ---- attention (dual-stream per CTA)
    dim3 ga(S/128, H, B);
    attn_mma<<<ga, 256, ATTN_SMEM>>>(Qf, K0f, K1f, Vf, xf);

    // ---- launch 3: output projection (single-A, fp32 out)
    GB go{};
    go.Ah[0]=xf; go.Al[0]=nullptr; go.W[0]=w+4*(size_t)D*D; go.bias[0]=bo;
    go.o0[0]=out; go.mode[0]=4;
    gemmU<<<dim3(D/128, M/128, 1), 256, GEMM_SMEM>>>(go);
}